// round 13
// baseline (speedup 1.0000x reference)
#include <cuda_runtime.h>
#include <cuda_fp16.h>
#include <cstdint>
#include <math.h>

// Problem constants (KGramMLPSeqModel: T=1024, B=4, V=32000, E=1024, K=3, H=2048)
#define T_N   1024
#define B_N   4
#define V_N   32000
#define E_N   1024
#define KCTX  3
#define H_N   2048
#define M_N   (T_N * B_N)      // 4096
#define K1_N  (KCTX * E_N)     // 3072

// ---------------------------------------------------------------------------
// Device scratch (__device__ globals per allocation-free rule)
// ---------------------------------------------------------------------------
__device__ __half g_hh[(size_t)M_N * H_N];    // h fp16 (M,H) K-major
__device__ __half g_wo[(size_t)V_N * H_N];    // Wout^T fp16 (V,H) K-major
__device__ __half g_ef[(size_t)V_N * E_N];    // embedding fp16 (V,E)
__device__ __half g_w1[(size_t)H_N * K1_N];   // W1^T fp16 (H,K1) K-major

// ---------------------------------------------------------------------------
// Helpers (baseline PTX only: plain compute_103 target)
// ---------------------------------------------------------------------------
__device__ __forceinline__ uint32_t smem_u32(const void* p) {
    uint32_t a;
    asm("{ .reg .u64 t; cvta.to.shared.u64 t, %1; cvt.u32.u64 %0, t; }" : "=r"(a) : "l"(p));
    return a;
}
#define CP16(dst, src) \
    asm volatile("cp.async.cg.shared.global [%0], [%1], 16;" :: "r"(dst), "l"(src) : "memory")
#define CP_COMMIT() asm volatile("cp.async.commit_group;" ::: "memory")
#define CP_WAIT1()  asm volatile("cp.async.wait_group 1;" ::: "memory")

#define LDSM4(r, addr) \
    asm volatile("ldmatrix.sync.aligned.m8n8.x4.shared.b16 {%0,%1,%2,%3}, [%4];" \
        : "=r"((r)[0]), "=r"((r)[1]), "=r"((r)[2]), "=r"((r)[3]) : "r"(addr))

#define MMA16816(d, a, b0, b1) \
    asm volatile("mma.sync.aligned.m16n8k16.row.col.f32.f16.f16.f32 " \
        "{%0,%1,%2,%3}, {%4,%5,%6,%7}, {%8,%9}, {%0,%1,%2,%3};" \
        : "+f"((d)[0]), "+f"((d)[1]), "+f"((d)[2]), "+f"((d)[3]) \
        : "r"((a)[0]), "r"((a)[1]), "r"((a)[2]), "r"((a)[3]), "r"(b0), "r"(b1))

// ---------------------------------------------------------------------------
// Prepass A: embedding fp32 -> fp16, same layout
// ---------------------------------------------------------------------------
__global__ __launch_bounds__(256)
void emb_convert(const float* __restrict__ emb)
{
    const size_t i4 = ((size_t)blockIdx.x * 256 + threadIdx.x) * 4;
    const float4 v = *reinterpret_cast<const float4*>(emb + i4);
    __half2* o = reinterpret_cast<__half2*>(g_ef + i4);
    o[0] = __half2(__float2half_rn(v.x), __float2half_rn(v.y));
    o[1] = __half2(__float2half_rn(v.z), __float2half_rn(v.w));
}

// ---------------------------------------------------------------------------
// Prepass B: transpose to fp16: in (R, C) fp32 -> out (C, R) fp16
// ---------------------------------------------------------------------------
__global__ __launch_bounds__(256)
void transpose_f16(const float* __restrict__ in,
                   __half* __restrict__ o,
                   int R, int C)
{
    __shared__ float tile[32][33];
    const int tx = threadIdx.x & 31;
    const int ty = threadIdx.x >> 5;          // 0..7
    const int cBase = blockIdx.x * 32;
    const int rBase = blockIdx.y * 32;

    #pragma unroll
    for (int j = 0; j < 4; j++)
        tile[ty + j * 8][tx] = in[(size_t)(rBase + ty + j * 8) * C + cBase + tx];
    __syncthreads();
    #pragma unroll
    for (int j = 0; j < 4; j++) {
        const int n = cBase + ty + j * 8;
        const int k = rBase + tx;
        o[(size_t)n * R + k] = __float2half_rn(tile[tx][ty + j * 8]);
    }
}

// ---------------------------------------------------------------------------
// Shared GEMM geometry: BM=128, BN=256, BK=32; 256 threads, 8 warps (2M x 4N),
// warp tile 64x64; single-product fp16; ROWB=80 conflict-free ldmatrix;
// 3-stage cp.async. Fewer warps => less redundant LDSM crossbar traffic
// (A loaded 4x not 8x): per-chunk LDSM bytes 96KB -> 64KB.
// ---------------------------------------------------------------------------
#define ROWB      80
#define A_BYTES   (128 * ROWB)     // 10240
#define B_BYTES   (256 * ROWB)     // 20480
#define OFF_A     0
#define OFF_B     A_BYTES
#define STAGE_B   (A_BYTES + B_BYTES)   // 30720
#define NSTAGE    3
#define GEMM_SMEM (NSTAGE * STAGE_B)    // 92160

// One 32-k chunk, warp tile 64x64 (acc[4][8][4]); single product.
#define COMPUTE_CHUNK(stb)                                                          \
    do {                                                                            \
        _Pragma("unroll")                                                           \
        for (int kk = 0; kk < 2; kk++) {                                            \
            const uint32_t colb = cselB + kk * 32;                                  \
            uint32_t af[4][4];                                                      \
            _Pragma("unroll")                                                       \
            for (int im = 0; im < 4; im++) {                                        \
                const uint32_t a = (stb) + OFF_A + (wm * 64 + im * 16 + rsel) * ROWB + colb; \
                LDSM4(af[im], a);                                                   \
            }                                                                       \
            uint32_t bf[4][4];                                                      \
            _Pragma("unroll")                                                       \
            for (int in = 0; in < 4; in++) {                                        \
                const uint32_t a = (stb) + OFF_B + (wn * 64 + in * 16 + rsel) * ROWB + colb; \
                LDSM4(bf[in], a);                                                   \
            }                                                                       \
            _Pragma("unroll")                                                       \
            for (int im = 0; im < 4; im++)                                          \
                _Pragma("unroll")                                                   \
                for (int jn = 0; jn < 8; jn++)                                      \
                    MMA16816(acc[im][jn], af[im], bf[jn >> 1][jn & 1], bf[jn >> 1][(jn & 1) + 2]); \
        }                                                                           \
    } while (0)

// ============================================================================
// GEMM1: h = silu(gather(emb) @ W1 + b1) -> fp16.  96 chunks.
// ============================================================================
#define G1_NCHUNK (K1_N / 32)   // 96

__global__ __launch_bounds__(256, 1)
void kgram_gemm1_mma(const int* __restrict__ tokens,
                     const __half* __restrict__ ef,
                     const __half* __restrict__ w1,
                     const float* __restrict__ b1)
{
    extern __shared__ char smem[];
    const uint32_t sb = smem_u32(smem);
    const int tid  = threadIdx.x;
    const int wid  = tid >> 5;
    const int lane = tid & 31;
    const int wm   = wid >> 2;          // 0..1 (M)
    const int wn   = wid & 3;           // 0..3 (N), 64 cols each

    const int rowBase = blockIdx.x * 128;
    const int colBase = blockIdx.y * 256;

    float acc[4][8][4];
    #pragma unroll
    for (int i = 0; i < 4; i++)
        #pragma unroll
        for (int j = 0; j < 8; j++)
            #pragma unroll
            for (int e = 0; e < 4; e++) acc[i][j][e] = 0.f;

    const int ldRow0 = tid >> 2;        // 0..63
    const int ldSeg  = tid & 3;
    const int ldCol  = ldSeg * 16;

    auto load_stage = [&](int c) {
        const int c0 = c * 32;
        const uint32_t stb = sb + (c % NSTAGE) * STAGE_B;
        const int kidx = c0 + ldSeg * 8;
        const int slot = kidx >> 10;
        const int off  = kidx & 1023;
        // A: gathered embedding rows (128 rows); 2 rows per thread
        #pragma unroll
        for (int it = 0; it < 2; it++) {
            const int row = ldRow0 + it * 64;
            const int r = rowBase + row;
            const int t = r >> 2;
            const int b = r & 3;
            const int tt = t - KCTX + slot;
            int tok = 0;
            if (tt >= 0) tok = tokens[tt * B_N + b];
            if (tok < 0) tok = 0;
            if (tok >= V_N) tok = V_N - 1;
            const size_t gA = (size_t)tok * E_N + off;
            CP16(stb + row * ROWB + ldCol + OFF_A, ef + gA);
        }
        // B: W1^T (256 rows); 4 rows per thread
        #pragma unroll
        for (int it = 0; it < 4; it++) {
            const int row = ldRow0 + it * 64;
            const size_t gB = (size_t)(colBase + row) * K1_N + c0 + ldSeg * 8;
            CP16(stb + row * ROWB + ldCol + OFF_B, w1 + gB);
        }
    };

    load_stage(0); CP_COMMIT();
    load_stage(1); CP_COMMIT();

    const int rsel  = lane & 15;
    const int cselB = (lane >> 4) * 16;

    for (int c = 0; c < G1_NCHUNK; c++) {
        CP_WAIT1();
        __syncthreads();
        if (c + 2 < G1_NCHUNK) load_stage(c + 2);
        CP_COMMIT();
        const uint32_t stb = sb + (c % NSTAGE) * STAGE_B;
        COMPUTE_CHUNK(stb);
    }

    // Epilogue: +b1, silu -> g_hh (fp16)
    const int mw = rowBase + wm * 64;
    const int nw = colBase + wn * 64;
    #pragma unroll
    for (int im = 0; im < 4; im++) {
        const int r0 = mw + im * 16 + (lane >> 2);
        #pragma unroll
        for (int jn = 0; jn < 8; jn++) {
            const int col = nw + jn * 8 + (lane & 3) * 2;
            const float2 bb = *reinterpret_cast<const float2*>(&b1[col]);
            float v00 = acc[im][jn][0] + bb.x;
            float v01 = acc[im][jn][1] + bb.y;
            float v10 = acc[im][jn][2] + bb.x;
            float v11 = acc[im][jn][3] + bb.y;
            v00 = v00 / (1.f + expf(-v00));
            v01 = v01 / (1.f + expf(-v01));
            v10 = v10 / (1.f + expf(-v10));
            v11 = v11 / (1.f + expf(-v11));
            *reinterpret_cast<__half2*>(g_hh + (size_t)r0 * H_N + col) =
                __half2(__float2half_rn(v00), __float2half_rn(v01));
            *reinterpret_cast<__half2*>(g_hh + (size_t)(r0 + 8) * H_N + col) =
                __half2(__float2half_rn(v10), __float2half_rn(v11));
        }
    }
}

// ============================================================================
// GEMM2: logits = h @ Wout + bout.  64 chunks.
// ============================================================================
#define G2_NCHUNK (H_N / 32)    // 64

__global__ __launch_bounds__(256, 1)
void kgram_gemm2_mma(const __half* __restrict__ hh,
                     const __half* __restrict__ wo,
                     const float* __restrict__ bout,
                     float* __restrict__ out)
{
    extern __shared__ char smem[];
    const uint32_t sb = smem_u32(smem);
    const int tid  = threadIdx.x;
    const int wid  = tid >> 5;
    const int lane = tid & 31;
    const int wm   = wid >> 2;          // 0..1
    const int wn   = wid & 3;           // 0..3

    const int rowBase = blockIdx.x * 128;   // M fastest -> B-strip reuse in L2
    const int colBase = blockIdx.y * 256;

    float acc[4][8][4];
    #pragma unroll
    for (int i = 0; i < 4; i++)
        #pragma unroll
        for (int j = 0; j < 8; j++)
            #pragma unroll
            for (int e = 0; e < 4; e++) acc[i][j][e] = 0.f;

    const int ldRow0 = tid >> 2;        // 0..63
    const int ldCol  = (tid & 3) * 16;
    const int kOff0  = ldCol >> 1;

    // Precomputed per-thread global base offsets (advance by +c*32 per chunk)
    const size_t baseA0 = (size_t)(rowBase + ldRow0)       * H_N + kOff0;
    const size_t baseA1 = (size_t)(rowBase + ldRow0 + 64)  * H_N + kOff0;
    const size_t baseB0 = (size_t)(colBase + ldRow0)       * H_N + kOff0;
    const size_t baseB1 = (size_t)(colBase + ldRow0 + 64)  * H_N + kOff0;
    const size_t baseB2 = (size_t)(colBase + ldRow0 + 128) * H_N + kOff0;
    const size_t baseB3 = (size_t)(colBase + ldRow0 + 192) * H_N + kOff0;
    const uint32_t dR0 = ldRow0 * ROWB + ldCol;
    const uint32_t dR1 = (ldRow0 + 64) * ROWB + ldCol;
    const uint32_t dR2 = (ldRow0 + 128) * ROWB + ldCol;
    const uint32_t dR3 = (ldRow0 + 192) * ROWB + ldCol;

    auto load_stage = [&](int c) {
        const int c0 = c * 32;
        const uint32_t stb = sb + (c % NSTAGE) * STAGE_B;
        CP16(stb + dR0 + OFF_A, hh + baseA0 + c0);
        CP16(stb + dR1 + OFF_A, hh + baseA1 + c0);
        CP16(stb + dR0 + OFF_B, wo + baseB0 + c0);
        CP16(stb + dR1 + OFF_B, wo + baseB1 + c0);
        CP16(stb + dR2 + OFF_B, wo + baseB2 + c0);
        CP16(stb + dR3 + OFF_B, wo + baseB3 + c0);
    };

    load_stage(0); CP_COMMIT();
    load_stage(1); CP_COMMIT();

    const int rsel  = lane & 15;
    const int cselB = (lane >> 4) * 16;

    for (int c = 0; c < G2_NCHUNK; c++) {
        CP_WAIT1();
        __syncthreads();
        if (c + 2 < G2_NCHUNK) load_stage(c + 2);
        CP_COMMIT();
        const uint32_t stb = sb + (c % NSTAGE) * STAGE_B;
        COMPUTE_CHUNK(stb);
    }

    // Epilogue: +bout -> gmem
    const int mw = rowBase + wm * 64;
    const int nw = colBase + wn * 64;
    #pragma unroll
    for (int im = 0; im < 4; im++) {
        const int r0 = mw + im * 16 + (lane >> 2);
        #pragma unroll
        for (int jn = 0; jn < 8; jn++) {
            const int col = nw + jn * 8 + (lane & 3) * 2;
            const float2 bb = *reinterpret_cast<const float2*>(&bout[col]);
            float2 o0, o1;
            o0.x = acc[im][jn][0] + bb.x;
            o0.y = acc[im][jn][1] + bb.y;
            o1.x = acc[im][jn][2] + bb.x;
            o1.y = acc[im][jn][3] + bb.y;
            *reinterpret_cast<float2*>(&out[(size_t)r0 * V_N + col])       = o0;
            *reinterpret_cast<float2*>(&out[(size_t)(r0 + 8) * V_N + col]) = o1;
        }
    }
}

// ---------------------------------------------------------------------------
// Launch
// ---------------------------------------------------------------------------
extern "C" void kernel_launch(void* const* d_in, const int* in_sizes, int n_in,
                              void* d_out, int out_size)
{
    const int*   tokens = (const int*)d_in[0];     // (T, B) int32
    const float* emb    = (const float*)d_in[1];   // (V, E)
    const float* W1     = (const float*)d_in[2];   // (K*E, H)
    const float* b1     = (const float*)d_in[3];   // (H,)
    const float* Wout   = (const float*)d_in[4];   // (H, V)
    const float* bout   = (const float*)d_in[5];   // (V,)
    float*       out    = (float*)d_out;           // (T, B, V) fp32

    __half *hh, *wo, *ef, *w1;
    cudaGetSymbolAddress((void**)&hh, g_hh);
    cudaGetSymbolAddress((void**)&wo, g_wo);
    cudaGetSymbolAddress((void**)&ef, g_ef);
    cudaGetSymbolAddress((void**)&w1, g_w1);

    // Prepasses
    emb_convert<<<(int)(((size_t)V_N * E_N) / 1024), 256>>>(emb);
    transpose_f16<<<dim3(H_N / 32, K1_N / 32), 256>>>(W1, w1, K1_N, H_N);
    transpose_f16<<<dim3(V_N / 32, H_N / 32), 256>>>(Wout, wo, H_N, V_N);

    // GEMM1 (fp16 1-product, gathered A) -> h fp16
    cudaFuncSetAttribute(kgram_gemm1_mma, cudaFuncAttributeMaxDynamicSharedMemorySize, GEMM_SMEM);
    kgram_gemm1_mma<<<dim3(M_N / 128, K1_N == 0 ? 1 : H_N / 256), 256, GEMM_SMEM>>>(tokens, ef, w1, b1);

    // GEMM2 (fp16 1-product)
    cudaFuncSetAttribute(kgram_gemm2_mma, cudaFuncAttributeMaxDynamicSharedMemorySize, GEMM_SMEM);
    kgram_gemm2_mma<<<dim3(M_N / 128, V_N / 256), 256, GEMM_SMEM>>>(hh, wo, bout, out);
}

// round 14
// speedup vs baseline: 1.1097x; 1.1097x over previous
#include <cuda_runtime.h>
#include <cuda_fp16.h>
#include <cstdint>
#include <math.h>

// Problem constants (KGramMLPSeqModel: T=1024, B=4, V=32000, E=1024, K=3, H=2048)
#define T_N   1024
#define B_N   4
#define V_N   32000
#define E_N   1024
#define KCTX  3
#define H_N   2048
#define M_N   (T_N * B_N)      // 4096
#define K1_N  (KCTX * E_N)     // 3072

// ---------------------------------------------------------------------------
// Device scratch (__device__ globals per allocation-free rule)
// ---------------------------------------------------------------------------
__device__ __half g_hh[(size_t)M_N * H_N];    // h fp16 (M,H) K-major
__device__ __half g_wo[(size_t)V_N * H_N];    // Wout^T fp16 (V,H) K-major
__device__ __half g_ef[(size_t)V_N * E_N];    // embedding fp16 (V,E)
__device__ __half g_w1[(size_t)H_N * K1_N];   // W1^T fp16 (H,K1) K-major

// ---------------------------------------------------------------------------
// Helpers (baseline PTX only: plain compute_103 target)
// ---------------------------------------------------------------------------
__device__ __forceinline__ uint32_t smem_u32(const void* p) {
    uint32_t a;
    asm("{ .reg .u64 t; cvta.to.shared.u64 t, %1; cvt.u32.u64 %0, t; }" : "=r"(a) : "l"(p));
    return a;
}
#define CP16(dst, src) \
    asm volatile("cp.async.cg.shared.global [%0], [%1], 16;" :: "r"(dst), "l"(src) : "memory")
#define CP_COMMIT() asm volatile("cp.async.commit_group;" ::: "memory")
#define CP_WAIT1()  asm volatile("cp.async.wait_group 1;" ::: "memory")

#define LDSM4(r, addr) \
    asm volatile("ldmatrix.sync.aligned.m8n8.x4.shared.b16 {%0,%1,%2,%3}, [%4];" \
        : "=r"((r)[0]), "=r"((r)[1]), "=r"((r)[2]), "=r"((r)[3]) : "r"(addr))

#define MMA16816(d, a, b0, b1) \
    asm volatile("mma.sync.aligned.m16n8k16.row.col.f32.f16.f16.f32 " \
        "{%0,%1,%2,%3}, {%4,%5,%6,%7}, {%8,%9}, {%0,%1,%2,%3};" \
        : "+f"((d)[0]), "+f"((d)[1]), "+f"((d)[2]), "+f"((d)[3]) \
        : "r"((a)[0]), "r"((a)[1]), "r"((a)[2]), "r"((a)[3]), "r"(b0), "r"(b1))

// ---------------------------------------------------------------------------
// Prepass A: embedding fp32 -> fp16, same layout
// ---------------------------------------------------------------------------
__global__ __launch_bounds__(256)
void emb_convert(const float* __restrict__ emb)
{
    const size_t i4 = ((size_t)blockIdx.x * 256 + threadIdx.x) * 4;
    const float4 v = *reinterpret_cast<const float4*>(emb + i4);
    __half2* o = reinterpret_cast<__half2*>(g_ef + i4);
    o[0] = __half2(__float2half_rn(v.x), __float2half_rn(v.y));
    o[1] = __half2(__float2half_rn(v.z), __float2half_rn(v.w));
}

// ---------------------------------------------------------------------------
// Prepass B: transpose to fp16: in (R, C) fp32 -> out (C, R) fp16
// ---------------------------------------------------------------------------
__global__ __launch_bounds__(256)
void transpose_f16(const float* __restrict__ in,
                   __half* __restrict__ o,
                   int R, int C)
{
    __shared__ float tile[32][33];
    const int tx = threadIdx.x & 31;
    const int ty = threadIdx.x >> 5;          // 0..7
    const int cBase = blockIdx.x * 32;
    const int rBase = blockIdx.y * 32;

    #pragma unroll
    for (int j = 0; j < 4; j++)
        tile[ty + j * 8][tx] = in[(size_t)(rBase + ty + j * 8) * C + cBase + tx];
    __syncthreads();
    #pragma unroll
    for (int j = 0; j < 4; j++) {
        const int n = cBase + ty + j * 8;
        const int k = rBase + tx;
        o[(size_t)n * R + k] = __float2half_rn(tile[tx][ty + j * 8]);
    }
}

// ---------------------------------------------------------------------------
// Shared GEMM geometry: BM=128, BN=128, BK=32; 256 threads, 8 warps (2M x 4N),
// warp tile 64x32; single-product fp16; ROWB=80 conflict-free ldmatrix;
// 3-stage cp.async. __launch_bounds__(256, 2) -> regs<=128 -> 2 CTAs/SM:
// two independently-synced warp groups per SM break the per-chunk lockstep
// (one CTA's LDSM phase overlaps the other CTA's MMA phase).
// ---------------------------------------------------------------------------
#define ROWB      80
#define A_BYTES   (128 * ROWB)     // 10240
#define B_BYTES   (128 * ROWB)     // 10240
#define OFF_A     0
#define OFF_B     A_BYTES
#define STAGE_B   (A_BYTES + B_BYTES)   // 20480
#define NSTAGE    3
#define GEMM_SMEM (NSTAGE * STAGE_B)    // 61440 (x2 CTAs = 123KB <= 227KB)

// One 32-k chunk, warp tile 64x32 (acc[4][4][4]); single product.
#define COMPUTE_CHUNK(stb)                                                          \
    do {                                                                            \
        _Pragma("unroll")                                                           \
        for (int kk = 0; kk < 2; kk++) {                                            \
            const uint32_t colb = cselB + kk * 32;                                  \
            uint32_t af[4][4];                                                      \
            _Pragma("unroll")                                                       \
            for (int im = 0; im < 4; im++) {                                        \
                const uint32_t a = (stb) + OFF_A + (wm * 64 + im * 16 + rsel) * ROWB + colb; \
                LDSM4(af[im], a);                                                   \
            }                                                                       \
            uint32_t bf[2][4];                                                      \
            _Pragma("unroll")                                                       \
            for (int in = 0; in < 2; in++) {                                        \
                const uint32_t a = (stb) + OFF_B + (wn * 32 + in * 16 + rsel) * ROWB + colb; \
                LDSM4(bf[in], a);                                                   \
            }                                                                       \
            _Pragma("unroll")                                                       \
            for (int im = 0; im < 4; im++)                                          \
                _Pragma("unroll")                                                   \
                for (int jn = 0; jn < 4; jn++)                                      \
                    MMA16816(acc[im][jn], af[im], bf[jn >> 1][jn & 1], bf[jn >> 1][(jn & 1) + 2]); \
        }                                                                           \
    } while (0)

// ============================================================================
// GEMM1: h = silu(gather(emb) @ W1 + b1) -> fp16.  96 chunks.
// ============================================================================
#define G1_NCHUNK (K1_N / 32)   // 96

__global__ __launch_bounds__(256, 2)
void kgram_gemm1_mma(const int* __restrict__ tokens,
                     const __half* __restrict__ ef,
                     const __half* __restrict__ w1,
                     const float* __restrict__ b1)
{
    extern __shared__ char smem[];
    const uint32_t sb = smem_u32(smem);
    const int tid  = threadIdx.x;
    const int wid  = tid >> 5;
    const int lane = tid & 31;
    const int wm   = wid >> 2;          // 0..1 (M)
    const int wn   = wid & 3;           // 0..3 (N), 32 cols each

    const int rowBase = blockIdx.x * 128;
    const int colBase = blockIdx.y * 128;

    float acc[4][4][4];
    #pragma unroll
    for (int i = 0; i < 4; i++)
        #pragma unroll
        for (int j = 0; j < 4; j++)
            #pragma unroll
            for (int e = 0; e < 4; e++) acc[i][j][e] = 0.f;

    const int ldRow0 = tid >> 2;        // 0..63
    const int ldSeg  = tid & 3;
    const int ldCol  = ldSeg * 16;

    auto load_stage = [&](int c) {
        const int c0 = c * 32;
        const uint32_t stb = sb + (c % NSTAGE) * STAGE_B;
        const int kidx = c0 + ldSeg * 8;
        const int slot = kidx >> 10;
        const int off  = kidx & 1023;
        // A: gathered embedding rows (128 rows); 2 rows per thread
        #pragma unroll
        for (int it = 0; it < 2; it++) {
            const int row = ldRow0 + it * 64;
            const int r = rowBase + row;
            const int t = r >> 2;
            const int b = r & 3;
            const int tt = t - KCTX + slot;
            int tok = 0;
            if (tt >= 0) tok = tokens[tt * B_N + b];
            if (tok < 0) tok = 0;
            if (tok >= V_N) tok = V_N - 1;
            const size_t gA = (size_t)tok * E_N + off;
            CP16(stb + row * ROWB + ldCol + OFF_A, ef + gA);
        }
        // B: W1^T (128 rows); 2 rows per thread
        #pragma unroll
        for (int it = 0; it < 2; it++) {
            const int row = ldRow0 + it * 64;
            const size_t gB = (size_t)(colBase + row) * K1_N + c0 + ldSeg * 8;
            CP16(stb + row * ROWB + ldCol + OFF_B, w1 + gB);
        }
    };

    load_stage(0); CP_COMMIT();
    load_stage(1); CP_COMMIT();

    const int rsel  = lane & 15;
    const int cselB = (lane >> 4) * 16;

    for (int c = 0; c < G1_NCHUNK; c++) {
        CP_WAIT1();
        __syncthreads();
        if (c + 2 < G1_NCHUNK) load_stage(c + 2);
        CP_COMMIT();
        const uint32_t stb = sb + (c % NSTAGE) * STAGE_B;
        COMPUTE_CHUNK(stb);
    }

    // Epilogue: +b1, silu -> g_hh (fp16)
    const int mw = rowBase + wm * 64;
    const int nw = colBase + wn * 32;
    #pragma unroll
    for (int im = 0; im < 4; im++) {
        const int r0 = mw + im * 16 + (lane >> 2);
        #pragma unroll
        for (int jn = 0; jn < 4; jn++) {
            const int col = nw + jn * 8 + (lane & 3) * 2;
            const float2 bb = *reinterpret_cast<const float2*>(&b1[col]);
            float v00 = acc[im][jn][0] + bb.x;
            float v01 = acc[im][jn][1] + bb.y;
            float v10 = acc[im][jn][2] + bb.x;
            float v11 = acc[im][jn][3] + bb.y;
            v00 = v00 / (1.f + expf(-v00));
            v01 = v01 / (1.f + expf(-v01));
            v10 = v10 / (1.f + expf(-v10));
            v11 = v11 / (1.f + expf(-v11));
            *reinterpret_cast<__half2*>(g_hh + (size_t)r0 * H_N + col) =
                __half2(__float2half_rn(v00), __float2half_rn(v01));
            *reinterpret_cast<__half2*>(g_hh + (size_t)(r0 + 8) * H_N + col) =
                __half2(__float2half_rn(v10), __float2half_rn(v11));
        }
    }
}

// ============================================================================
// GEMM2: logits = h @ Wout + bout.  64 chunks.
// ============================================================================
#define G2_NCHUNK (H_N / 32)    // 64

__global__ __launch_bounds__(256, 2)
void kgram_gemm2_mma(const __half* __restrict__ hh,
                     const __half* __restrict__ wo,
                     const float* __restrict__ bout,
                     float* __restrict__ out)
{
    extern __shared__ char smem[];
    const uint32_t sb = smem_u32(smem);
    const int tid  = threadIdx.x;
    const int wid  = tid >> 5;
    const int lane = tid & 31;
    const int wm   = wid >> 2;          // 0..1
    const int wn   = wid & 3;           // 0..3

    const int rowBase = blockIdx.x * 128;   // M fastest -> B-strip reuse in L2
    const int colBase = blockIdx.y * 128;

    float acc[4][4][4];
    #pragma unroll
    for (int i = 0; i < 4; i++)
        #pragma unroll
        for (int j = 0; j < 4; j++)
            #pragma unroll
            for (int e = 0; e < 4; e++) acc[i][j][e] = 0.f;

    const int ldRow0 = tid >> 2;        // 0..63
    const int ldCol  = (tid & 3) * 16;
    const int kOff0  = ldCol >> 1;

    // Precomputed per-thread global base offsets (advance by +c*32 per chunk)
    const size_t baseA0 = (size_t)(rowBase + ldRow0)      * H_N + kOff0;
    const size_t baseA1 = (size_t)(rowBase + ldRow0 + 64) * H_N + kOff0;
    const size_t baseB0 = (size_t)(colBase + ldRow0)      * H_N + kOff0;
    const size_t baseB1 = (size_t)(colBase + ldRow0 + 64) * H_N + kOff0;
    const uint32_t dR0 = ldRow0 * ROWB + ldCol;
    const uint32_t dR1 = (ldRow0 + 64) * ROWB + ldCol;

    auto load_stage = [&](int c) {
        const int c0 = c * 32;
        const uint32_t stb = sb + (c % NSTAGE) * STAGE_B;
        CP16(stb + dR0 + OFF_A, hh + baseA0 + c0);
        CP16(stb + dR1 + OFF_A, hh + baseA1 + c0);
        CP16(stb + dR0 + OFF_B, wo + baseB0 + c0);
        CP16(stb + dR1 + OFF_B, wo + baseB1 + c0);
    };

    load_stage(0); CP_COMMIT();
    load_stage(1); CP_COMMIT();

    const int rsel  = lane & 15;
    const int cselB = (lane >> 4) * 16;

    for (int c = 0; c < G2_NCHUNK; c++) {
        CP_WAIT1();
        __syncthreads();
        if (c + 2 < G2_NCHUNK) load_stage(c + 2);
        CP_COMMIT();
        const uint32_t stb = sb + (c % NSTAGE) * STAGE_B;
        COMPUTE_CHUNK(stb);
    }

    // Epilogue: +bout -> gmem
    const int mw = rowBase + wm * 64;
    const int nw = colBase + wn * 32;
    #pragma unroll
    for (int im = 0; im < 4; im++) {
        const int r0 = mw + im * 16 + (lane >> 2);
        #pragma unroll
        for (int jn = 0; jn < 4; jn++) {
            const int col = nw + jn * 8 + (lane & 3) * 2;
            const float2 bb = *reinterpret_cast<const float2*>(&bout[col]);
            float2 o0, o1;
            o0.x = acc[im][jn][0] + bb.x;
            o0.y = acc[im][jn][1] + bb.y;
            o1.x = acc[im][jn][2] + bb.x;
            o1.y = acc[im][jn][3] + bb.y;
            *reinterpret_cast<float2*>(&out[(size_t)r0 * V_N + col])       = o0;
            *reinterpret_cast<float2*>(&out[(size_t)(r0 + 8) * V_N + col]) = o1;
        }
    }
}

// ---------------------------------------------------------------------------
// Launch
// ---------------------------------------------------------------------------
extern "C" void kernel_launch(void* const* d_in, const int* in_sizes, int n_in,
                              void* d_out, int out_size)
{
    const int*   tokens = (const int*)d_in[0];     // (T, B) int32
    const float* emb    = (const float*)d_in[1];   // (V, E)
    const float* W1     = (const float*)d_in[2];   // (K*E, H)
    const float* b1     = (const float*)d_in[3];   // (H,)
    const float* Wout   = (const float*)d_in[4];   // (H, V)
    const float* bout   = (const float*)d_in[5];   // (V,)
    float*       out    = (float*)d_out;           // (T, B, V) fp32

    __half *hh, *wo, *ef, *w1;
    cudaGetSymbolAddress((void**)&hh, g_hh);
    cudaGetSymbolAddress((void**)&wo, g_wo);
    cudaGetSymbolAddress((void**)&ef, g_ef);
    cudaGetSymbolAddress((void**)&w1, g_w1);

    // Prepasses
    emb_convert<<<(int)(((size_t)V_N * E_N) / 1024), 256>>>(emb);
    transpose_f16<<<dim3(H_N / 32, K1_N / 32), 256>>>(W1, w1, K1_N, H_N);
    transpose_f16<<<dim3(V_N / 32, H_N / 32), 256>>>(Wout, wo, H_N, V_N);

    // GEMM1 (fp16 1-product, gathered A) -> h fp16
    cudaFuncSetAttribute(kgram_gemm1_mma, cudaFuncAttributeMaxDynamicSharedMemorySize, GEMM_SMEM);
    kgram_gemm1_mma<<<dim3(M_N / 128, H_N / 128), 256, GEMM_SMEM>>>(tokens, ef, w1, b1);

    // GEMM2 (fp16 1-product)
    cudaFuncSetAttribute(kgram_gemm2_mma, cudaFuncAttributeMaxDynamicSharedMemorySize, GEMM_SMEM);
    kgram_gemm2_mma<<<dim3(M_N / 128, V_N / 128), 256, GEMM_SMEM>>>(hh, wo, bout, out);
}

// round 15
// speedup vs baseline: 1.2150x; 1.0948x over previous
#include <cuda_runtime.h>
#include <cuda_fp16.h>
#include <cstdint>
#include <math.h>

// Problem constants (KGramMLPSeqModel: T=1024, B=4, V=32000, E=1024, K=3, H=2048)
#define T_N   1024
#define B_N   4
#define V_N   32000
#define E_N   1024
#define KCTX  3
#define H_N   2048
#define M_N   (T_N * B_N)      // 4096
#define K1_N  (KCTX * E_N)     // 3072

// ---------------------------------------------------------------------------
// Device scratch (__device__ globals per allocation-free rule)
// ---------------------------------------------------------------------------
__device__ __half g_hh[(size_t)M_N * H_N];    // h fp16 (M,H) K-major
__device__ __half g_wo[(size_t)V_N * H_N];    // Wout^T fp16 (V,H) K-major
__device__ __half g_ef[(size_t)V_N * E_N];    // embedding fp16 (V,E)
__device__ __half g_w1[(size_t)H_N * K1_N];   // W1^T fp16 (H,K1) K-major

// ---------------------------------------------------------------------------
// Helpers (baseline PTX only: plain compute_103 target)
// ---------------------------------------------------------------------------
__device__ __forceinline__ uint32_t smem_u32(const void* p) {
    uint32_t a;
    asm("{ .reg .u64 t; cvta.to.shared.u64 t, %1; cvt.u32.u64 %0, t; }" : "=r"(a) : "l"(p));
    return a;
}
#define CP16(dst, src) \
    asm volatile("cp.async.cg.shared.global [%0], [%1], 16;" :: "r"(dst), "l"(src) : "memory")
#define CP_COMMIT() asm volatile("cp.async.commit_group;" ::: "memory")
#define CP_WAIT0()  asm volatile("cp.async.wait_group 0;" ::: "memory")

#define LDSM4(r, addr) \
    asm volatile("ldmatrix.sync.aligned.m8n8.x4.shared.b16 {%0,%1,%2,%3}, [%4];" \
        : "=r"((r)[0]), "=r"((r)[1]), "=r"((r)[2]), "=r"((r)[3]) : "r"(addr))

#define MMA16816(d, a, b0, b1) \
    asm volatile("mma.sync.aligned.m16n8k16.row.col.f32.f16.f16.f32 " \
        "{%0,%1,%2,%3}, {%4,%5,%6,%7}, {%8,%9}, {%0,%1,%2,%3};" \
        : "+f"((d)[0]), "+f"((d)[1]), "+f"((d)[2]), "+f"((d)[3]) \
        : "r"((a)[0]), "r"((a)[1]), "r"((a)[2]), "r"((a)[3]), "r"(b0), "r"(b1))

// ---------------------------------------------------------------------------
// Prepass A: embedding fp32 -> fp16, same layout
// ---------------------------------------------------------------------------
__global__ __launch_bounds__(256)
void emb_convert(const float* __restrict__ emb)
{
    const size_t i4 = ((size_t)blockIdx.x * 256 + threadIdx.x) * 4;
    const float4 v = *reinterpret_cast<const float4*>(emb + i4);
    __half2* o = reinterpret_cast<__half2*>(g_ef + i4);
    o[0] = __half2(__float2half_rn(v.x), __float2half_rn(v.y));
    o[1] = __half2(__float2half_rn(v.z), __float2half_rn(v.w));
}

// ---------------------------------------------------------------------------
// Prepass B: transpose to fp16: in (R, C) fp32 -> out (C, R) fp16
// ---------------------------------------------------------------------------
__global__ __launch_bounds__(256)
void transpose_f16(const float* __restrict__ in,
                   __half* __restrict__ o,
                   int R, int C)
{
    __shared__ float tile[32][33];
    const int tx = threadIdx.x & 31;
    const int ty = threadIdx.x >> 5;          // 0..7
    const int cBase = blockIdx.x * 32;
    const int rBase = blockIdx.y * 32;

    #pragma unroll
    for (int j = 0; j < 4; j++)
        tile[ty + j * 8][tx] = in[(size_t)(rBase + ty + j * 8) * C + cBase + tx];
    __syncthreads();
    #pragma unroll
    for (int j = 0; j < 4; j++) {
        const int n = cBase + ty + j * 8;
        const int k = rBase + tx;
        o[(size_t)n * R + k] = __float2half_rn(tile[tx][ty + j * 8]);
    }
}

// ---------------------------------------------------------------------------
// Shared GEMM geometry: BM=128, BN=128, BK=64; 256 threads, 8 warps (2M x 4N),
// warp tile 64x32; single-product fp16; ROWB=144 (128B data + 16B pad, bank
// stride 36%32=4 -> conflict-free 8-row ldmatrix phases).
// 2-stage cp.async; __launch_bounds__(256,2) -> 2 CTAs/SM (lockstep break).
// BK=64 halves sync/wait count vs BK=32.
// ---------------------------------------------------------------------------
#define ROWB      144
#define A_BYTES   (128 * ROWB)     // 18432
#define B_BYTES   (128 * ROWB)     // 18432
#define OFF_A     0
#define OFF_B     A_BYTES
#define STAGE_B   (A_BYTES + B_BYTES)   // 36864
#define NSTAGE    2
#define GEMM_SMEM (NSTAGE * STAGE_B)    // 73728 (x2 CTAs = 147KB <= 227KB)

// One 64-k chunk, warp tile 64x32 (acc[4][4][4]); single product; 4 k16 groups.
#define COMPUTE_CHUNK(stb)                                                          \
    do {                                                                            \
        _Pragma("unroll")                                                           \
        for (int kk = 0; kk < 4; kk++) {                                            \
            const uint32_t colb = cselB + kk * 32;                                  \
            uint32_t af[4][4];                                                      \
            _Pragma("unroll")                                                       \
            for (int im = 0; im < 4; im++) {                                        \
                const uint32_t a = (stb) + OFF_A + (wm * 64 + im * 16 + rsel) * ROWB + colb; \
                LDSM4(af[im], a);                                                   \
            }                                                                       \
            uint32_t bf[2][4];                                                      \
            _Pragma("unroll")                                                       \
            for (int in = 0; in < 2; in++) {                                        \
                const uint32_t a = (stb) + OFF_B + (wn * 32 + in * 16 + rsel) * ROWB + colb; \
                LDSM4(bf[in], a);                                                   \
            }                                                                       \
            _Pragma("unroll")                                                       \
            for (int im = 0; im < 4; im++)                                          \
                _Pragma("unroll")                                                   \
                for (int jn = 0; jn < 4; jn++)                                      \
                    MMA16816(acc[im][jn], af[im], bf[jn >> 1][jn & 1], bf[jn >> 1][(jn & 1) + 2]); \
        }                                                                           \
    } while (0)

// ============================================================================
// GEMM1: h = silu(gather(emb) @ W1 + b1) -> fp16.  48 chunks of 64.
// ============================================================================
#define G1_NCHUNK (K1_N / 64)   // 48

__global__ __launch_bounds__(256, 2)
void kgram_gemm1_mma(const int* __restrict__ tokens,
                     const __half* __restrict__ ef,
                     const __half* __restrict__ w1,
                     const float* __restrict__ b1)
{
    extern __shared__ char smem[];
    const uint32_t sb = smem_u32(smem);
    const int tid  = threadIdx.x;
    const int wid  = tid >> 5;
    const int lane = tid & 31;
    const int wm   = wid >> 2;          // 0..1 (M)
    const int wn   = wid & 3;           // 0..3 (N), 32 cols each

    const int rowBase = blockIdx.x * 128;
    const int colBase = blockIdx.y * 128;

    float acc[4][4][4];
    #pragma unroll
    for (int i = 0; i < 4; i++)
        #pragma unroll
        for (int j = 0; j < 4; j++)
            #pragma unroll
            for (int e = 0; e < 4; e++) acc[i][j][e] = 0.f;

    // slot mapping: 128 rows x 8 segs of 16B; 256 threads -> 4 iters each
    const int ldRow0 = tid >> 3;        // 0..31 base row
    const int ldSeg  = tid & 7;         // 0..7
    const int segOff = ldSeg * 8;       // k-element offset within chunk

    auto load_stage = [&](int c) {
        const int c0 = c * 64;
        const uint32_t stb = sb + (c & 1) * STAGE_B;
        const int slot = c0 >> 10;          // same for all 64 k of this chunk
        const int off  = (c0 & 1023) + segOff;
        #pragma unroll
        for (int it = 0; it < 4; it++) {
            const int row = ldRow0 + it * 32;
            // A: gathered embedding
            const int r = rowBase + row;
            const int t = r >> 2;
            const int b = r & 3;
            const int tt = t - KCTX + slot;
            int tok = 0;
            if (tt >= 0) tok = tokens[tt * B_N + b];
            if (tok < 0) tok = 0;
            if (tok >= V_N) tok = V_N - 1;
            CP16(stb + row * ROWB + ldSeg * 16 + OFF_A, ef + (size_t)tok * E_N + off);
            // B: W1^T
            const size_t gB = (size_t)(colBase + row) * K1_N + c0 + segOff;
            CP16(stb + row * ROWB + ldSeg * 16 + OFF_B, w1 + gB);
        }
    };

    load_stage(0); CP_COMMIT();

    const int rsel  = lane & 15;
    const int cselB = (lane >> 4) * 16;

    for (int c = 0; c < G1_NCHUNK; c++) {
        CP_WAIT0();            // stage c resident (this thread's groups)
        __syncthreads();       // all warps done with compute(c-1), data visible
        if (c + 1 < G1_NCHUNK) { load_stage(c + 1); CP_COMMIT(); }
        const uint32_t stb = sb + (c & 1) * STAGE_B;
        COMPUTE_CHUNK(stb);
    }

    // Epilogue: +b1, silu -> g_hh (fp16)
    const int mw = rowBase + wm * 64;
    const int nw = colBase + wn * 32;
    #pragma unroll
    for (int im = 0; im < 4; im++) {
        const int r0 = mw + im * 16 + (lane >> 2);
        #pragma unroll
        for (int jn = 0; jn < 4; jn++) {
            const int col = nw + jn * 8 + (lane & 3) * 2;
            const float2 bb = *reinterpret_cast<const float2*>(&b1[col]);
            float v00 = acc[im][jn][0] + bb.x;
            float v01 = acc[im][jn][1] + bb.y;
            float v10 = acc[im][jn][2] + bb.x;
            float v11 = acc[im][jn][3] + bb.y;
            v00 = v00 / (1.f + expf(-v00));
            v01 = v01 / (1.f + expf(-v01));
            v10 = v10 / (1.f + expf(-v10));
            v11 = v11 / (1.f + expf(-v11));
            *reinterpret_cast<__half2*>(g_hh + (size_t)r0 * H_N + col) =
                __half2(__float2half_rn(v00), __float2half_rn(v01));
            *reinterpret_cast<__half2*>(g_hh + (size_t)(r0 + 8) * H_N + col) =
                __half2(__float2half_rn(v10), __float2half_rn(v11));
        }
    }
}

// ============================================================================
// GEMM2: logits = h @ Wout + bout.  32 chunks of 64.
// ============================================================================
#define G2_NCHUNK (H_N / 64)    // 32

__global__ __launch_bounds__(256, 2)
void kgram_gemm2_mma(const __half* __restrict__ hh,
                     const __half* __restrict__ wo,
                     const float* __restrict__ bout,
                     float* __restrict__ out)
{
    extern __shared__ char smem[];
    const uint32_t sb = smem_u32(smem);
    const int tid  = threadIdx.x;
    const int wid  = tid >> 5;
    const int lane = tid & 31;
    const int wm   = wid >> 2;          // 0..1
    const int wn   = wid & 3;           // 0..3

    const int rowBase = blockIdx.x * 128;   // M fastest -> B-strip reuse in L2
    const int colBase = blockIdx.y * 128;

    float acc[4][4][4];
    #pragma unroll
    for (int i = 0; i < 4; i++)
        #pragma unroll
        for (int j = 0; j < 4; j++)
            #pragma unroll
            for (int e = 0; e < 4; e++) acc[i][j][e] = 0.f;

    const int ldRow0 = tid >> 3;        // 0..31
    const int ldSeg  = tid & 7;
    const int segOff = ldSeg * 8;

    auto load_stage = [&](int c) {
        const int c0 = c * 64;
        const uint32_t stb = sb + (c & 1) * STAGE_B;
        #pragma unroll
        for (int it = 0; it < 4; it++) {
            const int row = ldRow0 + it * 32;
            const uint32_t d = stb + row * ROWB + ldSeg * 16;
            CP16(d + OFF_A, hh + (size_t)(rowBase + row) * H_N + c0 + segOff);
            CP16(d + OFF_B, wo + (size_t)(colBase + row) * H_N + c0 + segOff);
        }
    };

    load_stage(0); CP_COMMIT();

    const int rsel  = lane & 15;
    const int cselB = (lane >> 4) * 16;

    for (int c = 0; c < G2_NCHUNK; c++) {
        CP_WAIT0();
        __syncthreads();
        if (c + 1 < G2_NCHUNK) { load_stage(c + 1); CP_COMMIT(); }
        const uint32_t stb = sb + (c & 1) * STAGE_B;
        COMPUTE_CHUNK(stb);
    }

    // Epilogue: +bout -> gmem
    const int mw = rowBase + wm * 64;
    const int nw = colBase + wn * 32;
    #pragma unroll
    for (int im = 0; im < 4; im++) {
        const int r0 = mw + im * 16 + (lane >> 2);
        #pragma unroll
        for (int jn = 0; jn < 4; jn++) {
            const int col = nw + jn * 8 + (lane & 3) * 2;
            const float2 bb = *reinterpret_cast<const float2*>(&bout[col]);
            float2 o0, o1;
            o0.x = acc[im][jn][0] + bb.x;
            o0.y = acc[im][jn][1] + bb.y;
            o1.x = acc[im][jn][2] + bb.x;
            o1.y = acc[im][jn][3] + bb.y;
            *reinterpret_cast<float2*>(&out[(size_t)r0 * V_N + col])       = o0;
            *reinterpret_cast<float2*>(&out[(size_t)(r0 + 8) * V_N + col]) = o1;
        }
    }
}

// ---------------------------------------------------------------------------
// Launch
// ---------------------------------------------------------------------------
extern "C" void kernel_launch(void* const* d_in, const int* in_sizes, int n_in,
                              void* d_out, int out_size)
{
    const int*   tokens = (const int*)d_in[0];     // (T, B) int32
    const float* emb    = (const float*)d_in[1];   // (V, E)
    const float* W1     = (const float*)d_in[2];   // (K*E, H)
    const float* b1     = (const float*)d_in[3];   // (H,)
    const float* Wout   = (const float*)d_in[4];   // (H, V)
    const float* bout   = (const float*)d_in[5];   // (V,)
    float*       out    = (float*)d_out;           // (T, B, V) fp32

    __half *hh, *wo, *ef, *w1;
    cudaGetSymbolAddress((void**)&hh, g_hh);
    cudaGetSymbolAddress((void**)&wo, g_wo);
    cudaGetSymbolAddress((void**)&ef, g_ef);
    cudaGetSymbolAddress((void**)&w1, g_w1);

    // Prepasses
    emb_convert<<<(int)(((size_t)V_N * E_N) / 1024), 256>>>(emb);
    transpose_f16<<<dim3(H_N / 32, K1_N / 32), 256>>>(W1, w1, K1_N, H_N);
    transpose_f16<<<dim3(V_N / 32, H_N / 32), 256>>>(Wout, wo, H_N, V_N);

    // GEMM1 (fp16 1-product, gathered A) -> h fp16
    cudaFuncSetAttribute(kgram_gemm1_mma, cudaFuncAttributeMaxDynamicSharedMemorySize, GEMM_SMEM);
    kgram_gemm1_mma<<<dim3(M_N / 128, H_N / 128), 256, GEMM_SMEM>>>(tokens, ef, w1, b1);

    // GEMM2 (fp16 1-product)
    cudaFuncSetAttribute(kgram_gemm2_mma, cudaFuncAttributeMaxDynamicSharedMemorySize, GEMM_SMEM);
    kgram_gemm2_mma<<<dim3(M_N / 128, V_N / 128), 256, GEMM_SMEM>>>(hh, wo, bout, out);
}